// round 1
// baseline (speedup 1.0000x reference)
#include <cuda_runtime.h>
#include <math.h>

// Problem constants
#define BATCH 8
#define CTXN  4096
#define QSTN  512
#define E_DIM 300
#define H_DIM 128

// Tiling
#define BM 64          // ctx rows per CTA / q rows per tile
#define EK 75          // E-chunk (300 = 4*75)
#define NTHREADS 256

// smem pitches (odd / conflict-free)
#define PITCH_STAGE 77   // EK + 2
#define PITCH_H 129      // H_DIM + 1
#define PITCH_S 517      // QSTN + 5

// smem layout (floats) for attn kernel
#define OFF_L 0
#define SZ_L (BM * PITCH_H)                      // 8256
#define OFF_S (OFF_L + SZ_L)                     // 8256
#define SZ_S (BM * PITCH_S)                      // 33088
#define OFF_STAGE (OFF_S + SZ_S)                 // 41344
#define SZ_STAGE (BM * PITCH_STAGE + H_DIM * PITCH_STAGE)  // 14784
#define SMEM_FLOATS (OFF_STAGE + SZ_STAGE)       // 56128 -> 224512 bytes

// scratch: qst_logits [8*512, 128] fp32 (2 MB)
__device__ float g_qst_logits[BATCH * QSTN * H_DIM];

// ---------------------------------------------------------------------------
// Kernel 1: qst_logits = relu(qst @ W^T + b)   [4096 rows x 300] -> [4096 x 128]
// ---------------------------------------------------------------------------
__global__ __launch_bounds__(NTHREADS)
void qst_logits_kernel(const float* __restrict__ qst,
                       const float* __restrict__ W,
                       const float* __restrict__ bias) {
    extern __shared__ float sm[];
    float* sA = sm;                         // [BM][PITCH_STAGE]
    float* sW = sm + BM * PITCH_STAGE;      // [H_DIM][PITCH_STAGE]

    const int row0 = blockIdx.x * BM;
    const int tid = threadIdx.x;
    const int tx = tid & 15;
    const int ty = tid >> 4;

    float acc[4][8];
#pragma unroll
    for (int i = 0; i < 4; i++)
#pragma unroll
        for (int j = 0; j < 8; j++) acc[i][j] = 0.f;

    for (int e0 = 0; e0 < E_DIM; e0 += EK) {
        __syncthreads();
        for (int idx = tid; idx < BM * EK; idx += NTHREADS) {
            int r = idx / EK, e = idx - r * EK;
            sA[r * PITCH_STAGE + e] = qst[(size_t)(row0 + r) * E_DIM + e0 + e];
        }
        for (int idx = tid; idx < H_DIM * EK; idx += NTHREADS) {
            int h = idx / EK, e = idx - h * EK;
            sW[h * PITCH_STAGE + e] = W[(size_t)h * E_DIM + e0 + e];
        }
        __syncthreads();
#pragma unroll 5
        for (int k = 0; k < EK; k++) {
            float a[4], w[8];
#pragma unroll
            for (int i = 0; i < 4; i++) a[i] = sA[(ty + 16 * i) * PITCH_STAGE + k];
#pragma unroll
            for (int j = 0; j < 8; j++) w[j] = sW[(tx + 16 * j) * PITCH_STAGE + k];
#pragma unroll
            for (int i = 0; i < 4; i++)
#pragma unroll
                for (int j = 0; j < 8; j++) acc[i][j] += a[i] * w[j];
        }
    }

#pragma unroll
    for (int i = 0; i < 4; i++) {
        int r = row0 + ty + 16 * i;
#pragma unroll
        for (int j = 0; j < 8; j++) {
            int h = tx + 16 * j;
            g_qst_logits[(size_t)r * H_DIM + h] = fmaxf(acc[i][j] + bias[h], 0.f);
        }
    }
}

// ---------------------------------------------------------------------------
// Kernel 2: fused ctx_logits -> scores -> softmax -> PV
// grid: (CTXN/BM, BATCH); one CTA = 64 ctx rows of one batch
// ---------------------------------------------------------------------------
__global__ __launch_bounds__(NTHREADS)
void attn_kernel(const float* __restrict__ ctx,
                 const int* __restrict__ mask,
                 const float* __restrict__ W,
                 const float* __restrict__ bias,
                 float* __restrict__ out) {
    extern __shared__ float sm[];
    float* Lsm   = sm + OFF_L;      // ctx_logits [BM][PITCH_H]
    float* Ssm   = sm + OFF_S;      // scores     [BM][PITCH_S]
    float* stage = sm + OFF_STAGE;  // staging
    float* sA = stage;                       // [BM][PITCH_STAGE]
    float* sW = stage + BM * PITCH_STAGE;    // [H_DIM][PITCH_STAGE]

    const int b  = blockIdx.y;
    const int c0 = blockIdx.x * BM;
    const int tid = threadIdx.x;
    const int tx = tid & 15;
    const int ty = tid >> 4;

    const float* ctxb = ctx + ((size_t)b * CTXN + c0) * E_DIM;
    const float* qlb  = g_qst_logits + (size_t)b * QSTN * H_DIM;
    const int* maskb  = mask + (size_t)b * QSTN;

    // ---------------- Phase 1: L = relu(ctx_tile @ W^T + b) ----------------
    {
        float acc[4][8];
#pragma unroll
        for (int i = 0; i < 4; i++)
#pragma unroll
            for (int j = 0; j < 8; j++) acc[i][j] = 0.f;

        for (int e0 = 0; e0 < E_DIM; e0 += EK) {
            __syncthreads();
            for (int idx = tid; idx < BM * EK; idx += NTHREADS) {
                int r = idx / EK, e = idx - r * EK;
                sA[r * PITCH_STAGE + e] = ctxb[(size_t)r * E_DIM + e0 + e];
            }
            for (int idx = tid; idx < H_DIM * EK; idx += NTHREADS) {
                int h = idx / EK, e = idx - h * EK;
                sW[h * PITCH_STAGE + e] = W[(size_t)h * E_DIM + e0 + e];
            }
            __syncthreads();
#pragma unroll 5
            for (int k = 0; k < EK; k++) {
                float a[4], w[8];
#pragma unroll
                for (int i = 0; i < 4; i++) a[i] = sA[(ty + 16 * i) * PITCH_STAGE + k];
#pragma unroll
                for (int j = 0; j < 8; j++) w[j] = sW[(tx + 16 * j) * PITCH_STAGE + k];
#pragma unroll
                for (int i = 0; i < 4; i++)
#pragma unroll
                    for (int j = 0; j < 8; j++) acc[i][j] += a[i] * w[j];
            }
        }
#pragma unroll
        for (int i = 0; i < 4; i++)
#pragma unroll
            for (int j = 0; j < 8; j++) {
                int h = tx + 16 * j;
                Lsm[(ty + 16 * i) * PITCH_H + h] = fmaxf(acc[i][j] + bias[h], 0.f);
            }
    }
    __syncthreads();

    // ---------------- Phase 2: S = L @ Qb^T  (with mask) ----------------
    for (int qt = 0; qt < QSTN / BM; qt++) {
        for (int idx = tid; idx < BM * H_DIM; idx += NTHREADS) {
            int q = idx >> 7, h = idx & 127;
            stage[q * PITCH_H + h] = qlb[(size_t)(qt * BM + q) * H_DIM + h];
        }
        __syncthreads();

        float acc2[4][4];
#pragma unroll
        for (int i = 0; i < 4; i++)
#pragma unroll
            for (int j = 0; j < 4; j++) acc2[i][j] = 0.f;

#pragma unroll 4
        for (int h = 0; h < H_DIM; h++) {
            float a[4], qv[4];
#pragma unroll
            for (int i = 0; i < 4; i++) a[i] = Lsm[(ty + 16 * i) * PITCH_H + h];
#pragma unroll
            for (int j = 0; j < 4; j++) qv[j] = stage[(tx + 16 * j) * PITCH_H + h];
#pragma unroll
            for (int i = 0; i < 4; i++)
#pragma unroll
                for (int j = 0; j < 4; j++) acc2[i][j] += a[i] * qv[j];
        }
#pragma unroll
        for (int j = 0; j < 4; j++) {
            int q = qt * BM + tx + 16 * j;
            bool valid = (maskb[q] != 0);
#pragma unroll
            for (int i = 0; i < 4; i++) {
                Ssm[(ty + 16 * i) * PITCH_S + q] = valid ? acc2[i][j] : -1e30f;
            }
        }
        __syncthreads();
    }

    // ---------------- Softmax over q (rows of S) ----------------
    {
        const int warp = tid >> 5;
        const int lane = tid & 31;
        for (int r = warp * 8; r < warp * 8 + 8; r++) {
            float* row = Ssm + r * PITCH_S;
            float mx = -1e30f;
            for (int q = lane; q < QSTN; q += 32) mx = fmaxf(mx, row[q]);
#pragma unroll
            for (int o = 16; o > 0; o >>= 1) mx = fmaxf(mx, __shfl_xor_sync(0xffffffffu, mx, o));
            float sum = 0.f;
            for (int q = lane; q < QSTN; q += 32) {
                float e = __expf(row[q] - mx);
                row[q] = e;
                sum += e;
            }
#pragma unroll
            for (int o = 16; o > 0; o >>= 1) sum += __shfl_xor_sync(0xffffffffu, sum, o);
            float inv = 1.f / sum;
            for (int q = lane; q < QSTN; q += 32) row[q] *= inv;
        }
    }
    __syncthreads();

    // ---------------- Phase 3: out = P @ Qb ----------------
    {
        float acc3[4][8];
#pragma unroll
        for (int i = 0; i < 4; i++)
#pragma unroll
            for (int j = 0; j < 8; j++) acc3[i][j] = 0.f;

        for (int qt = 0; qt < QSTN / BM; qt++) {
            for (int idx = tid; idx < BM * H_DIM; idx += NTHREADS) {
                int q = idx >> 7, h = idx & 127;
                stage[q * PITCH_H + h] = qlb[(size_t)(qt * BM + q) * H_DIM + h];
            }
            __syncthreads();
#pragma unroll 4
            for (int q = 0; q < BM; q++) {
                float p[4], qv[8];
#pragma unroll
                for (int i = 0; i < 4; i++) p[i] = Ssm[(ty + 16 * i) * PITCH_S + qt * BM + q];
#pragma unroll
                for (int j = 0; j < 8; j++) qv[j] = stage[q * PITCH_H + tx + 16 * j];
#pragma unroll
                for (int i = 0; i < 4; i++)
#pragma unroll
                    for (int j = 0; j < 8; j++) acc3[i][j] += p[i] * qv[j];
            }
            __syncthreads();
        }

#pragma unroll
        for (int i = 0; i < 4; i++) {
            size_t orow = ((size_t)b * CTXN + c0 + ty + 16 * i) * H_DIM;
#pragma unroll
            for (int j = 0; j < 8; j++) {
                out[orow + tx + 16 * j] = acc3[i][j];
            }
        }
    }
}

// ---------------------------------------------------------------------------
extern "C" void kernel_launch(void* const* d_in, const int* in_sizes, int n_in,
                              void* d_out, int out_size) {
    const float* ctx  = (const float*)d_in[0];
    const float* qst  = (const float*)d_in[1];
    const int*   mask = (const int*)d_in[2];
    const float* W    = (const float*)d_in[3];
    const float* bias = (const float*)d_in[4];
    float* out = (float*)d_out;

    cudaFuncSetAttribute(qst_logits_kernel,
                         cudaFuncAttributeMaxDynamicSharedMemorySize,
                         SZ_STAGE * (int)sizeof(float));
    cudaFuncSetAttribute(attn_kernel,
                         cudaFuncAttributeMaxDynamicSharedMemorySize,
                         SMEM_FLOATS * (int)sizeof(float));

    qst_logits_kernel<<<(BATCH * QSTN) / BM, NTHREADS, SZ_STAGE * sizeof(float)>>>(qst, W, bias);
    attn_kernel<<<dim3(CTXN / BM, BATCH), NTHREADS, SMEM_FLOATS * sizeof(float)>>>(ctx, mask, W, bias, out);
}

// round 2
// speedup vs baseline: 1.4094x; 1.4094x over previous
#include <cuda_runtime.h>
#include <math.h>

// Problem constants
#define BATCH 8
#define CTXN  4096
#define QSTN  512
#define E_DIM 300
#define H_DIM 128

// Tiling
#define BM 64          // ctx rows per CTA
#define QT 64          // q-tile width
#define EK 75          // E-chunk (300 = 4*75)
#define NTHREADS 256

// smem pitches
#define PITCH_STAGE 77   // EK + 2
#define PITCH_H 129      // H_DIM + 1
#define PITCH_P 80       // P tile pitch (stride-16 col writes -> disjoint banks)

// smem layout (floats) for attn kernel
#define OFF_L 0
#define SZ_L (BM * PITCH_H)                       // 8256
#define OFF_WORK (OFF_L + SZ_L)
// phase-1 staging: sA [BM][77] + sW [128][77] = 14784 floats
// flash loop:      stage [QT][129] (8256) + Psm [BM][80] (5120) = 13376 floats
#define SZ_WORK (BM * PITCH_STAGE + H_DIM * PITCH_STAGE)   // 14784
#define SMEM_FLOATS (OFF_WORK + SZ_WORK)          // 23040 floats = 92160 B

// scratch: qst_logits [8*512, 128] fp32 (2 MB)
__device__ float g_qst_logits[BATCH * QSTN * H_DIM];

// ---------------------------------------------------------------------------
// Kernel 1: qst_logits = relu(qst @ W^T + b)
// ---------------------------------------------------------------------------
__global__ __launch_bounds__(NTHREADS)
void qst_logits_kernel(const float* __restrict__ qst,
                       const float* __restrict__ W,
                       const float* __restrict__ bias) {
    extern __shared__ float sm[];
    float* sA = sm;                         // [BM][PITCH_STAGE]
    float* sW = sm + BM * PITCH_STAGE;      // [H_DIM][PITCH_STAGE]

    const int row0 = blockIdx.x * BM;
    const int tid = threadIdx.x;
    const int tx = tid & 15;
    const int ty = tid >> 4;

    float acc[4][8];
#pragma unroll
    for (int i = 0; i < 4; i++)
#pragma unroll
        for (int j = 0; j < 8; j++) acc[i][j] = 0.f;

    for (int e0 = 0; e0 < E_DIM; e0 += EK) {
        __syncthreads();
        for (int idx = tid; idx < BM * EK; idx += NTHREADS) {
            int r = idx / EK, e = idx - r * EK;
            sA[r * PITCH_STAGE + e] = qst[(size_t)(row0 + r) * E_DIM + e0 + e];
        }
        for (int idx = tid; idx < H_DIM * EK; idx += NTHREADS) {
            int h = idx / EK, e = idx - h * EK;
            sW[h * PITCH_STAGE + e] = W[(size_t)h * E_DIM + e0 + e];
        }
        __syncthreads();
#pragma unroll 5
        for (int k = 0; k < EK; k++) {
            float a[4], w[8];
#pragma unroll
            for (int i = 0; i < 4; i++) a[i] = sA[(ty + 16 * i) * PITCH_STAGE + k];
#pragma unroll
            for (int j = 0; j < 8; j++) w[j] = sW[(tx + 16 * j) * PITCH_STAGE + k];
#pragma unroll
            for (int i = 0; i < 4; i++)
#pragma unroll
                for (int j = 0; j < 8; j++) acc[i][j] += a[i] * w[j];
        }
    }

#pragma unroll
    for (int i = 0; i < 4; i++) {
        int r = row0 + ty + 16 * i;
#pragma unroll
        for (int j = 0; j < 8; j++) {
            int h = tx + 16 * j;
            g_qst_logits[(size_t)r * H_DIM + h] = fmaxf(acc[i][j] + bias[h], 0.f);
        }
    }
}

// ---------------------------------------------------------------------------
// Kernel 2: fused ctx_logits -> flash-style online-softmax attention
// grid: (CTXN/BM, BATCH); 2 CTAs/SM
// ---------------------------------------------------------------------------
__global__ __launch_bounds__(NTHREADS, 2)
void attn_kernel(const float* __restrict__ ctx,
                 const int* __restrict__ mask,
                 const float* __restrict__ W,
                 const float* __restrict__ bias,
                 float* __restrict__ out) {
    extern __shared__ float sm[];
    float* Lsm   = sm + OFF_L;      // ctx_logits [BM][PITCH_H]
    float* work  = sm + OFF_WORK;
    // phase-1 view
    float* sA = work;                        // [BM][PITCH_STAGE]
    float* sW = work + BM * PITCH_STAGE;     // [H_DIM][PITCH_STAGE]
    // flash-loop view
    float* stage = work;                     // [QT][PITCH_H]
    float* Psm   = work + QT * PITCH_H;      // [BM][PITCH_P]

    const int b  = blockIdx.y;
    const int c0 = blockIdx.x * BM;
    const int tid = threadIdx.x;
    const int tx = tid & 15;
    const int ty = tid >> 4;

    const float* ctxb = ctx + ((size_t)b * CTXN + c0) * E_DIM;
    const float* qlb  = g_qst_logits + (size_t)b * QSTN * H_DIM;
    const int* maskb  = mask + (size_t)b * QSTN;

    // ---------------- Phase 1: L = relu(ctx_tile @ W^T + b) ----------------
    {
        float acc[4][8];
#pragma unroll
        for (int i = 0; i < 4; i++)
#pragma unroll
            for (int j = 0; j < 8; j++) acc[i][j] = 0.f;

        for (int e0 = 0; e0 < E_DIM; e0 += EK) {
            __syncthreads();
            for (int idx = tid; idx < BM * EK; idx += NTHREADS) {
                int r = idx / EK, e = idx - r * EK;
                sA[r * PITCH_STAGE + e] = ctxb[(size_t)r * E_DIM + e0 + e];
            }
            for (int idx = tid; idx < H_DIM * EK; idx += NTHREADS) {
                int h = idx / EK, e = idx - h * EK;
                sW[h * PITCH_STAGE + e] = W[(size_t)h * E_DIM + e0 + e];
            }
            __syncthreads();
#pragma unroll 5
            for (int k = 0; k < EK; k++) {
                float a[4], w[8];
#pragma unroll
                for (int i = 0; i < 4; i++) a[i] = sA[(ty + 16 * i) * PITCH_STAGE + k];
#pragma unroll
                for (int j = 0; j < 8; j++) w[j] = sW[(tx + 16 * j) * PITCH_STAGE + k];
#pragma unroll
                for (int i = 0; i < 4; i++)
#pragma unroll
                    for (int j = 0; j < 8; j++) acc[i][j] += a[i] * w[j];
            }
        }
        __syncthreads();  // done with sA/sW before Lsm+flash reuse of work
#pragma unroll
        for (int i = 0; i < 4; i++)
#pragma unroll
            for (int j = 0; j < 8; j++) {
                int h = tx + 16 * j;
                Lsm[(ty + 16 * i) * PITCH_H + h] = fmaxf(acc[i][j] + bias[h], 0.f);
            }
    }
    __syncthreads();

    // ---------------- Flash loop over q-tiles ----------------
    float m_run[4], s_run[4], acc3[4][8];
#pragma unroll
    for (int i = 0; i < 4; i++) { m_run[i] = -1e30f; s_run[i] = 0.f; }
#pragma unroll
    for (int i = 0; i < 4; i++)
#pragma unroll
        for (int j = 0; j < 8; j++) acc3[i][j] = 0.f;

    for (int qt = 0; qt < QSTN / QT; qt++) {
        // stage Q-tile [QT][H_DIM]
        for (int idx = tid; idx < QT * H_DIM; idx += NTHREADS) {
            int q = idx >> 7, h = idx & 127;
            stage[q * PITCH_H + h] = qlb[(size_t)(qt * QT + q) * H_DIM + h];
        }
        __syncthreads();

        // S-tile = L @ Qt^T (registers)
        float acc2[4][4];
#pragma unroll
        for (int i = 0; i < 4; i++)
#pragma unroll
            for (int j = 0; j < 4; j++) acc2[i][j] = 0.f;

#pragma unroll 4
        for (int h = 0; h < H_DIM; h++) {
            float a[4], qv[4];
#pragma unroll
            for (int i = 0; i < 4; i++) a[i] = Lsm[(ty + 16 * i) * PITCH_H + h];
#pragma unroll
            for (int j = 0; j < 4; j++) qv[j] = stage[(tx + 16 * j) * PITCH_H + h];
#pragma unroll
            for (int i = 0; i < 4; i++)
#pragma unroll
                for (int j = 0; j < 4; j++) acc2[i][j] += a[i] * qv[j];
        }

        // mask
#pragma unroll
        for (int j = 0; j < 4; j++) {
            if (maskb[qt * QT + tx + 16 * j] == 0) {
#pragma unroll
                for (int i = 0; i < 4; i++) acc2[i][j] = -1e30f;
            }
        }

        // online softmax update: row spread over 16 tx-lanes (same half-warp)
        float m_new[4], corr[4];
#pragma unroll
        for (int i = 0; i < 4; i++) {
            float mx = fmaxf(fmaxf(acc2[i][0], acc2[i][1]), fmaxf(acc2[i][2], acc2[i][3]));
#pragma unroll
            for (int o = 8; o > 0; o >>= 1) mx = fmaxf(mx, __shfl_xor_sync(0xffffffffu, mx, o));
            m_new[i] = fmaxf(m_run[i], mx);
            corr[i] = __expf(m_run[i] - m_new[i]);
            m_run[i] = m_new[i];

            float psum = 0.f;
#pragma unroll
            for (int j = 0; j < 4; j++) {
                acc2[i][j] = __expf(acc2[i][j] - m_new[i]);
                psum += acc2[i][j];
            }
#pragma unroll
            for (int o = 8; o > 0; o >>= 1) psum += __shfl_xor_sync(0xffffffffu, psum, o);
            s_run[i] = s_run[i] * corr[i] + psum;
#pragma unroll
            for (int j = 0; j < 8; j++) acc3[i][j] *= corr[i];
        }

        // write P-tile to smem
#pragma unroll
        for (int i = 0; i < 4; i++)
#pragma unroll
            for (int j = 0; j < 4; j++)
                Psm[(ty + 16 * i) * PITCH_P + tx + 16 * j] = acc2[i][j];
        __syncthreads();

        // acc3 += P @ Qt
#pragma unroll 4
        for (int q = 0; q < QT; q++) {
            float p[4], qv[8];
#pragma unroll
            for (int i = 0; i < 4; i++) p[i] = Psm[(ty + 16 * i) * PITCH_P + q];
#pragma unroll
            for (int j = 0; j < 8; j++) qv[j] = stage[q * PITCH_H + tx + 16 * j];
#pragma unroll
            for (int i = 0; i < 4; i++)
#pragma unroll
                for (int j = 0; j < 8; j++) acc3[i][j] += p[i] * qv[j];
        }
        __syncthreads();
    }

    // ---------------- Final: normalize & store ----------------
#pragma unroll
    for (int i = 0; i < 4; i++) {
        float inv = 1.f / s_run[i];
        size_t orow = ((size_t)b * CTXN + c0 + ty + 16 * i) * H_DIM;
#pragma unroll
        for (int j = 0; j < 8; j++) {
            out[orow + tx + 16 * j] = acc3[i][j] * inv;
        }
    }
}

// ---------------------------------------------------------------------------
extern "C" void kernel_launch(void* const* d_in, const int* in_sizes, int n_in,
                              void* d_out, int out_size) {
    const float* ctx  = (const float*)d_in[0];
    const float* qst  = (const float*)d_in[1];
    const int*   mask = (const int*)d_in[2];
    const float* W    = (const float*)d_in[3];
    const float* bias = (const float*)d_in[4];
    float* out = (float*)d_out;

    cudaFuncSetAttribute(qst_logits_kernel,
                         cudaFuncAttributeMaxDynamicSharedMemorySize,
                         SZ_WORK * (int)sizeof(float));
    cudaFuncSetAttribute(attn_kernel,
                         cudaFuncAttributeMaxDynamicSharedMemorySize,
                         SMEM_FLOATS * (int)sizeof(float));

    qst_logits_kernel<<<(BATCH * QSTN) / BM, NTHREADS, SZ_WORK * sizeof(float)>>>(qst, W, bias);
    attn_kernel<<<dim3(CTXN / BM, BATCH), NTHREADS, SMEM_FLOATS * sizeof(float)>>>(ctx, mask, W, bias, out);
}

// round 4
// speedup vs baseline: 5.7515x; 4.0808x over previous
#include <cuda_runtime.h>
#include <cuda_fp16.h>
#include <cuda_bf16.h>
#include <cstdint>

#define B_    8
#define CTXN  4096
#define QSTN  512
#define E_DIM 300
#define H_DIM 128
#define L2E   1.44269504088896340736f

// f16 qst logits, [q,h] and [h,q] layouts (2 MB)
__device__ __align__(16) __half g_Q [B_ * QSTN * H_DIM];
__device__ __align__(16) __half g_Qt[B_ * H_DIM * QSTN];

// ---------------------------------------------------------------------------
// helpers
// ---------------------------------------------------------------------------
__device__ __forceinline__ uint32_t smem_u32(const void* p) {
    uint32_t a;
    asm("{ .reg .u64 t; cvta.to.shared.u64 t, %1; cvt.u32.u64 %0, t; }" : "=r"(a) : "l"(p));
    return a;
}
__device__ __forceinline__ void ldsm4(uint32_t* r, uint32_t addr) {
    asm volatile("ldmatrix.sync.aligned.m8n8.x4.shared.b16 {%0,%1,%2,%3}, [%4];"
                 : "=r"(r[0]), "=r"(r[1]), "=r"(r[2]), "=r"(r[3]) : "r"(addr));
}
__device__ __forceinline__ void ldsm2(uint32_t* r, uint32_t addr) {
    asm volatile("ldmatrix.sync.aligned.m8n8.x2.shared.b16 {%0,%1}, [%2];"
                 : "=r"(r[0]), "=r"(r[1]) : "r"(addr));
}
__device__ __forceinline__ void mma_bf16(float* c, const uint32_t* a, const uint32_t* b) {
    asm volatile("mma.sync.aligned.m16n8k16.row.col.f32.bf16.bf16.f32 "
                 "{%0,%1,%2,%3}, {%4,%5,%6,%7}, {%8,%9}, {%0,%1,%2,%3};"
                 : "+f"(c[0]), "+f"(c[1]), "+f"(c[2]), "+f"(c[3])
                 : "r"(a[0]), "r"(a[1]), "r"(a[2]), "r"(a[3]), "r"(b[0]), "r"(b[1]));
}
__device__ __forceinline__ void mma_f16(float* c, const uint32_t* a, const uint32_t* b) {
    asm volatile("mma.sync.aligned.m16n8k16.row.col.f32.f16.f16.f32 "
                 "{%0,%1,%2,%3}, {%4,%5,%6,%7}, {%8,%9}, {%0,%1,%2,%3};"
                 : "+f"(c[0]), "+f"(c[1]), "+f"(c[2]), "+f"(c[3])
                 : "r"(a[0]), "r"(a[1]), "r"(a[2]), "r"(a[3]), "r"(b[0]), "r"(b[1]));
}
__device__ __forceinline__ float ex2f(float x) {
    float y; asm("ex2.approx.f32 %0, %1;" : "=f"(y) : "f"(x)); return y;
}
// split float4 into packed bf16 hi/lo (2x uint2)
__device__ __forceinline__ void split4(float4 v, uint2& hv, uint2& lv) {
    float t[4] = {v.x, v.y, v.z, v.w};
    uint32_t hh[2], ll[2];
#pragma unroll
    for (int p = 0; p < 2; p++) {
        __nv_bfloat16 a = __float2bfloat16_rn(t[2 * p]);
        __nv_bfloat16 c = __float2bfloat16_rn(t[2 * p + 1]);
        __nv_bfloat162 h2; h2.x = a; h2.y = c;
        __nv_bfloat162 l2;
        l2.x = __float2bfloat16_rn(t[2 * p] - __bfloat162float(a));
        l2.y = __float2bfloat16_rn(t[2 * p + 1] - __bfloat162float(c));
        hh[p] = *reinterpret_cast<uint32_t*>(&h2);
        ll[p] = *reinterpret_cast<uint32_t*>(&l2);
    }
    hv = make_uint2(hh[0], hh[1]);
    lv = make_uint2(ll[0], ll[1]);
}

// ---------------------------------------------------------------------------
// Kernel 1: qst logits (FFMA) -> f16, [q,h] + [h,q]
// ---------------------------------------------------------------------------
#define K1_BM 32
#define K1_P  77
__global__ __launch_bounds__(256)
void qst_logits_kernel(const float* __restrict__ qst,
                       const float* __restrict__ W,
                       const float* __restrict__ bias) {
    extern __shared__ float sm1[];
    float* sA = sm1;                     // [32][77]
    float* sW = sm1 + K1_BM * K1_P;      // [128][77]
    const int tid = threadIdx.x, tx = tid & 15, ty = tid >> 4;
    const int row0 = blockIdx.x * K1_BM;

    float acc[2][8];
#pragma unroll
    for (int i = 0; i < 2; i++)
#pragma unroll
        for (int j = 0; j < 8; j++) acc[i][j] = 0.f;

    for (int e0 = 0; e0 < E_DIM; e0 += 75) {
        __syncthreads();
        for (int i = tid; i < K1_BM * 75; i += 256) {
            int r = i / 75, e = i - r * 75;
            sA[r * K1_P + e] = qst[(size_t)(row0 + r) * E_DIM + e0 + e];
        }
        for (int i = tid; i < H_DIM * 75; i += 256) {
            int h = i / 75, e = i - h * 75;
            sW[h * K1_P + e] = W[(size_t)h * E_DIM + e0 + e];
        }
        __syncthreads();
#pragma unroll 5
        for (int k = 0; k < 75; k++) {
            float a0 = sA[ty * K1_P + k], a1 = sA[(ty + 16) * K1_P + k], w[8];
#pragma unroll
            for (int j = 0; j < 8; j++) w[j] = sW[(tx + 16 * j) * K1_P + k];
#pragma unroll
            for (int j = 0; j < 8; j++) { acc[0][j] += a0 * w[j]; acc[1][j] += a1 * w[j]; }
        }
    }

#pragma unroll
    for (int i = 0; i < 2; i++) {
        int r = row0 + ty + 16 * i;
        int bb = r >> 9, q = r & 511;
#pragma unroll
        for (int j = 0; j < 8; j++) {
            int h = tx + 16 * j;
            float v = fmaxf(acc[i][j] + bias[h], 0.f);
            __half hf = __float2half_rn(v);
            g_Q [(size_t)r * H_DIM + h] = hf;
            g_Qt[((size_t)bb * H_DIM + h) * QSTN + q] = hf;
        }
    }
}

// ---------------------------------------------------------------------------
// Kernel 2: HMMA fused dense + flash attention. 1 CTA = 128 ctx rows, 8 warps.
// ---------------------------------------------------------------------------
#define OFF_BIAS 0
#define OFF_MADD 512
#define OFF_ONES 2560        // 8 rows * 272B = 2176
#define OFF_STG  4864
// phase1: Ah@STG, Al@+18432, Wh@+36864, Wl@+55296 (pitch 144B)
// flash:  Q@STG (128*272=34816), Qt@STG+34816 (pitch 272B)
#define SM2_BYTES (4864 + 73728)

__global__ __launch_bounds__(256, 1)
void attn_kernel(const float* __restrict__ ctx,
                 const int* __restrict__ mask,
                 const float* __restrict__ W,
                 const float* __restrict__ bias,
                 float* __restrict__ out) {
    extern __shared__ char sm[];
    const uint32_t base = smem_u32(sm);
    const int tid = threadIdx.x, w = tid >> 5, l = tid & 31;
    const int grp = l >> 2, qd = l & 3;
    const int asel = (l >> 4) & 1, bsel = (l >> 3) & 1, brow = l & 7;
    const int b = blockIdx.y, c0 = blockIdx.x * 128;

    float* biasSm = (float*)(sm + OFF_BIAS);
    float* maddSm = (float*)(sm + OFF_MADD);

    for (int i = tid; i < H_DIM; i += 256) biasSm[i] = bias[i];
    for (int i = tid; i < QSTN; i += 256)
        maddSm[i] = mask[b * QSTN + i] ? 0.f : -2e30f;
    for (int i = tid; i < 8 * 136; i += 256) {
        int r = i / 136, c = i - r * 136;
        ((__half*)(sm + OFF_ONES + r * 272))[c] =
            (r == 0) ? __float2half(1.f) : __float2half(0.f);
    }

    // ---------------- Phase 1: acc = ctx_tile @ W^T (split bf16, 3 passes) ---
    const float* ctxb = ctx + ((size_t)b * CTXN + c0) * E_DIM;
    float acc[16][4];
#pragma unroll
    for (int j = 0; j < 16; j++)
#pragma unroll
        for (int i = 0; i < 4; i++) acc[j][i] = 0.f;

    const uint32_t sAh = base + OFF_STG;
    const uint32_t sAl = sAh + 18432;
    const uint32_t sWh = sAh + 36864;
    const uint32_t sWl = sAh + 55296;

    for (int ck = 0; ck < 5; ck++) {
        const int k0 = ck * 64;
        const int nk4 = (ck < 4) ? 16 : 11;
        const int nks = (ck < 4) ? 4 : 3;
        __syncthreads();
        for (int idx = tid; idx < 2048; idx += 256) {
            int row = idx >> 4, c4 = idx & 15;
            float4 av = make_float4(0.f, 0.f, 0.f, 0.f);
            float4 wv = make_float4(0.f, 0.f, 0.f, 0.f);
            if (c4 < nk4) {
                av = *(const float4*)(ctxb + (size_t)row * E_DIM + k0 + c4 * 4);
                wv = *(const float4*)(W + (size_t)row * E_DIM + k0 + c4 * 4);
            }
            uint32_t o = (uint32_t)(row * 144 + c4 * 8);
            uint2 h2, l2;
            split4(av, h2, l2);
            *(uint2*)(sm + OFF_STG + o) = h2;
            *(uint2*)(sm + OFF_STG + 18432 + o) = l2;
            split4(wv, h2, l2);
            *(uint2*)(sm + OFF_STG + 36864 + o) = h2;
            *(uint2*)(sm + OFF_STG + 55296 + o) = l2;
        }
        __syncthreads();

        const uint32_t arow = (uint32_t)(w * 16 + (l & 15));
#pragma unroll
        for (int kk = 0; kk < 4; kk++) {
            if (kk >= nks) break;
            uint32_t Ah[4], Al[4];
            uint32_t aoff = arow * 144 + (uint32_t)((kk * 16 + asel * 8) * 2);
            ldsm4(Ah, sAh + aoff);
            ldsm4(Al, sAl + aoff);
#pragma unroll
            for (int j = 0; j < 16; j++) {
                uint32_t Bh[2], Bl[2];
                uint32_t boff = (uint32_t)((8 * j + brow) * 144 + (kk * 16 + bsel * 8) * 2);
                ldsm2(Bh, sWh + boff);
                ldsm2(Bl, sWl + boff);
                mma_bf16(acc[j], Ah, Bh);
                mma_bf16(acc[j], Ah, Bl);
                mma_bf16(acc[j], Al, Bh);
            }
        }
    }

    // ---------------- bias + relu -> L fragments (f16, registers) ----------
    uint32_t Lf[8][4];
#pragma unroll
    for (int j = 0; j < 16; j++) {
        float2 bb = *(float2*)(biasSm + 8 * j + 2 * qd);
        float v0 = fmaxf(acc[j][0] + bb.x, 0.f);
        float v1 = fmaxf(acc[j][1] + bb.y, 0.f);
        float v2 = fmaxf(acc[j][2] + bb.x, 0.f);
        float v3 = fmaxf(acc[j][3] + bb.y, 0.f);
        __half2 ha = __floats2half2_rn(v0, v1);
        __half2 hb = __floats2half2_rn(v2, v3);
        Lf[j >> 1][(j & 1) * 2]     = *reinterpret_cast<uint32_t*>(&ha);
        Lf[j >> 1][(j & 1) * 2 + 1] = *reinterpret_cast<uint32_t*>(&hb);
    }

    // ---------------- Flash loop over 4 q-tiles of 128 ----------------------
    const uint32_t sQ  = base + OFF_STG;
    const uint32_t sQt = sQ + 34816;
    const uint32_t sOn = base + OFF_ONES;

    float m2a = -1e30f, m2b = -1e30f;
    float o_acc[17][4];
#pragma unroll
    for (int j = 0; j < 17; j++)
#pragma unroll
        for (int i = 0; i < 4; i++) o_acc[j][i] = 0.f;

    for (int t = 0; t < 4; t++) {
        __syncthreads();
        for (int idx = tid; idx < 2048; idx += 256) {
            int row = idx >> 4, s8 = idx & 15;
            uint4 vq = *(const uint4*)(g_Q + ((size_t)(b * QSTN + t * 128 + row)) * H_DIM + s8 * 8);
            uint4 vt = *(const uint4*)(g_Qt + ((size_t)(b * H_DIM + row)) * QSTN + t * 128 + s8 * 8);
            *(uint4*)(sm + OFF_STG + row * 272 + s8 * 16) = vq;
            *(uint4*)(sm + OFF_STG + 34816 + row * 272 + s8 * 16) = vt;
        }
        __syncthreads();

        // S = L @ Q^T
        float sacc[16][4];
#pragma unroll
        for (int j = 0; j < 16; j++)
#pragma unroll
            for (int i = 0; i < 4; i++) sacc[j][i] = 0.f;
#pragma unroll
        for (int kk = 0; kk < 8; kk++) {
#pragma unroll
            for (int j = 0; j < 16; j++) {
                uint32_t Bq[2];
                ldsm2(Bq, sQ + (uint32_t)((8 * j + brow) * 272 + (kk * 16 + bsel * 8) * 2));
                mma_f16(sacc[j], Lf[kk], Bq);
            }
        }

        // mask + row max
        float ma = -1e30f, mb = -1e30f;
#pragma unroll
        for (int j = 0; j < 16; j++) {
            float2 md = *(float2*)(maddSm + t * 128 + 8 * j + 2 * qd);
            sacc[j][0] += md.x; sacc[j][1] += md.y;
            sacc[j][2] += md.x; sacc[j][3] += md.y;
            ma = fmaxf(ma, fmaxf(sacc[j][0], sacc[j][1]));
            mb = fmaxf(mb, fmaxf(sacc[j][2], sacc[j][3]));
        }
        ma = fmaxf(ma, __shfl_xor_sync(0xffffffffu, ma, 1));
        ma = fmaxf(ma, __shfl_xor_sync(0xffffffffu, ma, 2));
        mb = fmaxf(mb, __shfl_xor_sync(0xffffffffu, mb, 1));
        mb = fmaxf(mb, __shfl_xor_sync(0xffffffffu, mb, 2));

        float m2a_n = fmaxf(m2a, ma * L2E);
        float m2b_n = fmaxf(m2b, mb * L2E);
        float ca = ex2f(m2a - m2a_n);
        float cb = ex2f(m2b - m2b_n);
        m2a = m2a_n; m2b = m2b_n;

        // P = exp2(S*log2e - m2)  (packed f16 a-fragments)
        uint32_t Pf[8][4];
#pragma unroll
        for (int j = 0; j < 16; j++) {
            float x0 = fmaf(sacc[j][0], L2E, -m2a);
            float x1 = fmaf(sacc[j][1], L2E, -m2a);
            float x2 = fmaf(sacc[j][2], L2E, -m2b);
            float x3 = fmaf(sacc[j][3], L2E, -m2b);
            __half2 pa = h2exp2(__floats2half2_rn(x0, x1));
            __half2 pb = h2exp2(__floats2half2_rn(x2, x3));
            Pf[j >> 1][(j & 1) * 2]     = *reinterpret_cast<uint32_t*>(&pa);
            Pf[j >> 1][(j & 1) * 2 + 1] = *reinterpret_cast<uint32_t*>(&pb);
        }

        // rescale O, then O += P @ Qt  (tile 16 = ones column -> row sums)
#pragma unroll
        for (int j = 0; j < 17; j++) {
            o_acc[j][0] *= ca; o_acc[j][1] *= ca;
            o_acc[j][2] *= cb; o_acc[j][3] *= cb;
        }
#pragma unroll
        for (int kk = 0; kk < 8; kk++) {
#pragma unroll
            for (int j = 0; j < 17; j++) {
                uint32_t Bv[2];
                uint32_t addr = (j < 16)
                    ? sQt + (uint32_t)((8 * j + brow) * 272 + (kk * 16 + bsel * 8) * 2)
                    : sOn + (uint32_t)(brow * 272 + (kk * 16 + bsel * 8) * 2);
                ldsm2(Bv, addr);
                mma_f16(o_acc[j], Pf[kk], Bv);
            }
        }
    }

    // ---------------- normalize + store -------------------------------------
    float sa = __shfl_sync(0xffffffffu, o_acc[16][0], l & ~3);
    float sb = __shfl_sync(0xffffffffu, o_acc[16][2], l & ~3);
    float ia = 1.f / sa, ib = 1.f / sb;
    const int r0 = c0 + w * 16 + grp;
    float* ob = out + (size_t)b * CTXN * H_DIM;
#pragma unroll
    for (int j = 0; j < 16; j++) {
        int col = 8 * j + 2 * qd;
        float2 v0 = make_float2(o_acc[j][0] * ia, o_acc[j][1] * ia);
        float2 v1 = make_float2(o_acc[j][2] * ib, o_acc[j][3] * ib);
        *(float2*)(ob + (size_t)r0 * H_DIM + col) = v0;
        *(float2*)(ob + (size_t)(r0 + 8) * H_DIM + col) = v1;
    }
}

// ---------------------------------------------------------------------------
extern "C" void kernel_launch(void* const* d_in, const int* in_sizes, int n_in,
                              void* d_out, int out_size) {
    const float* ctx  = (const float*)d_in[0];
    const float* qst  = (const float*)d_in[1];
    const int*   mask = (const int*)d_in[2];
    const float* W    = (const float*)d_in[3];
    const float* bias = (const float*)d_in[4];
    float* out = (float*)d_out;

    const int k1_smem = (K1_BM + H_DIM) * K1_P * (int)sizeof(float);
    cudaFuncSetAttribute(qst_logits_kernel,
                         cudaFuncAttributeMaxDynamicSharedMemorySize, k1_smem);
    cudaFuncSetAttribute(attn_kernel,
                         cudaFuncAttributeMaxDynamicSharedMemorySize, SM2_BYTES);

    qst_logits_kernel<<<(B_ * QSTN) / K1_BM, 256, k1_smem>>>(qst, W, bias);
    attn_kernel<<<dim3(CTXN / 128, B_), 256, SM2_BYTES>>>(ctx, mask, W, bias, out);
}